// round 14
// baseline (speedup 1.0000x reference)
#include <cuda_runtime.h>

#define BSZ   8
#define NPTS  4096
#define CIN   128
#define COUT  256
#define MCTR  1024
#define SSAMP 64
#define NTILES 1024        // GEMM tiles: (NPTS/64)*(COUT/128)*BSZ
#define CHUNK  8           // centers per MP chunk
#define NCHUNK (BSZ * MCTR / CHUNK)   // 1024

// Scratch (static device globals: no allocations allowed)
__device__ float g_pre[BSZ * NPTS * COUT];   // [b][n][o]  33.5 MB
__device__ int   g_fps[BSZ * MCTR];
__device__ int   g_smid[BSZ];                // SMs hosting FPS blocks
__device__ int   g_ready;                    // FPS blocks that published smid
__device__ int   g_tile;                     // GEMM tile queue head
__device__ int   g_gdone;                    // completed GEMM tiles
__device__ int   g_mpq;                      // MP chunk queue head
__device__ int   g_prog[BSZ];                // FPS progress (coarse, 16 stores)

// Exact reference arithmetic: squares then left-to-right sum, no FMA contraction.
__device__ __forceinline__ float d2_rn(float ax, float ay, float az,
                                       float bx, float by, float bz) {
    float dx = ax - bx, dy = ay - by, dz = az - bz;
    return __fadd_rn(__fadd_rn(__fmul_rn(dx, dx), __fmul_rn(dy, dy)),
                     __fmul_rn(dz, dz));
}

// ---- packed f32x2 helpers (per-lane IEEE rn: bit-identical to scalar) ----
__device__ __forceinline__ unsigned long long pack2(float lo, float hi) {
    unsigned long long r;
    asm("mov.b64 %0, {%1, %2};" : "=l"(r) : "f"(lo), "f"(hi));
    return r;
}
__device__ __forceinline__ void unpack2(unsigned long long v, float& lo, float& hi) {
    asm("mov.b64 {%0, %1}, %2;" : "=f"(lo), "=f"(hi) : "l"(v));
}
__device__ __forceinline__ unsigned long long add2(unsigned long long a,
                                                   unsigned long long b) {
    unsigned long long r;
    asm("add.rn.f32x2 %0, %1, %2;" : "=l"(r) : "l"(a), "l"(b));
    return r;
}
__device__ __forceinline__ unsigned long long mul2(unsigned long long a,
                                                   unsigned long long b) {
    unsigned long long r;
    asm("mul.rn.f32x2 %0, %1, %2;" : "=l"(r) : "l"(a), "l"(b));
    return r;
}

__device__ __forceinline__ void st_rel(int* p, int v) {
    asm volatile("st.release.gpu.global.s32 [%0], %1;" :: "l"(p), "r"(v) : "memory");
}
__device__ __forceinline__ int ld_acq(const int* p) {
    int v;
    asm volatile("ld.acquire.gpu.global.s32 %0, [%1];" : "=r"(v) : "l"(p) : "memory");
    return v;
}
__device__ __forceinline__ int my_smid() {
    int s; asm("mov.u32 %0, %%smid;" : "=r"(s)); return s;
}

// ---------------------------------------------------------------------------
__global__ void reset_kernel() {
    if (threadIdx.x == 0) { g_ready = 0; g_tile = 0; g_gdone = 0; g_mpq = 0; }
    if (threadIdx.x < BSZ) g_prog[threadIdx.x] = 0;
}

// ---------------------------------------------------------------------------
// FPS (r10 champion + COARSE progress publication: one release store every
// 64 iterations — 16 per batch total, so poll traffic cannot contest the
// line on the hot path, unlike r11's per-iteration store).
// ---------------------------------------------------------------------------
__device__ void fps_body(const float* __restrict__ xyz, int b) {
    const int tid = threadIdx.x;
    const int lane = tid & 31, warp = tid >> 5;

    __shared__ int s_wv[8];
    __shared__ int s_widx[2];

    if (tid == 0) {
        g_smid[b] = my_smid();
        __threadfence();
        atomicAdd(&g_ready, 1);
    }

    const float* p = xyz + b * NPTS * 3;

    unsigned long long px2[8], py2[8], pz2[8];
    float mind[16];
#pragma unroll
    for (int j = 0; j < 8; j++) {
        int n0 = (2 * j) * 256 + tid;
        int n1 = (2 * j + 1) * 256 + tid;
        px2[j] = pack2(p[3 * n0 + 0], p[3 * n1 + 0]);
        py2[j] = pack2(p[3 * n0 + 1], p[3 * n1 + 1]);
        pz2[j] = pack2(p[3 * n0 + 2], p[3 * n1 + 2]);
        mind[2 * j] = 1e10f; mind[2 * j + 1] = 1e10f;
    }
    if (tid == 0) s_widx[0] = 0;   // idx[0] = 0
    __syncthreads();

    for (int t = 1; t < MCTR; t++) {
        const int Iv = s_widx[(t - 1) & 1];
        if (tid == 0) {
            g_fps[b * MCTR + t - 1] = Iv;
            if ((t & 63) == 0) st_rel(&g_prog[b], t);   // entries [0,t) valid
            s_widx[t & 1] = 0x7fffffff;
        }
        const float lx = __ldg(p + 3 * Iv + 0);
        const float ly = __ldg(p + 3 * Iv + 1);
        const float lz = __ldg(p + 3 * Iv + 2);
        const unsigned long long nlx2 = pack2(-lx, -lx);
        const unsigned long long nly2 = pack2(-ly, -ly);
        const unsigned long long nlz2 = pack2(-lz, -lz);

#pragma unroll
        for (int j = 0; j < 8; j++) {
            unsigned long long dx2 = add2(px2[j], nlx2);
            unsigned long long dy2 = add2(py2[j], nly2);
            unsigned long long dz2 = add2(pz2[j], nlz2);
            unsigned long long s2 = add2(add2(mul2(dx2, dx2), mul2(dy2, dy2)),
                                         mul2(dz2, dz2));
            float s0, s1; unpack2(s2, s0, s1);
            mind[2 * j]     = fminf(mind[2 * j],     s0);
            mind[2 * j + 1] = fminf(mind[2 * j + 1], s1);
        }

        float m01 = fmaxf(mind[0], mind[1]),   m23 = fmaxf(mind[2], mind[3]);
        float m45 = fmaxf(mind[4], mind[5]),   m67 = fmaxf(mind[6], mind[7]);
        float m89 = fmaxf(mind[8], mind[9]),   mab = fmaxf(mind[10], mind[11]);
        float mcd = fmaxf(mind[12], mind[13]), mef = fmaxf(mind[14], mind[15]);
        float q0 = fmaxf(m01, m23), q1 = fmaxf(m45, m67);
        float q2 = fmaxf(m89, mab), q3 = fmaxf(mcd, mef);
        float best = fmaxf(fmaxf(q0, q1), fmaxf(q2, q3));

        const int tb   = __float_as_int(best);
        const int wmax = __reduce_max_sync(0xffffffffu, tb);
        if (lane == 0) s_wv[warp] = wmax;
        __syncthreads();

        int vb = (lane < 8) ? s_wv[lane] : (int)0x80000000;
        const int bmax = __reduce_max_sync(0xffffffffu, vb);

        if (tb == bmax) {  // rare: winner thread(s) resolve lowest index
            int n = 0x7fffffff;
#pragma unroll
            for (int k = 15; k >= 0; k--)
                if (__float_as_int(mind[k]) == bmax) n = k * 256 + tid;
            atomicMin(&s_widx[t & 1], n);
        }
        __syncthreads();
    }
    if (tid == 0) {
        g_fps[b * MCTR + MCTR - 1] = s_widx[(MCTR - 1) & 1];
        st_rel(&g_prog[b], MCTR);
    }
}

// ---------------------------------------------------------------------------
// One GEMM tile (r10 champion): pre[b][n][o] = sum_c feat[b][c][n] * W[o][c].
// ---------------------------------------------------------------------------
__device__ void gemm_tile(const float* __restrict__ feat,
                          const float* __restrict__ W, int gid,
                          float sF[32][65], float sW[32][129]) {
    const int b    = gid >> 7;
    const int rest = gid & 127;
    const int o0   = (rest & 1) * 128;
    const int n0   = (rest >> 1) * 64;

    const int tid = threadIdx.x;
    const int tx = tid & 15;
    const int ty = tid >> 4;

    float acc[4][8];
#pragma unroll
    for (int i = 0; i < 4; i++)
#pragma unroll
        for (int j = 0; j < 8; j++) acc[i][j] = 0.f;

    const float* fb = feat + b * CIN * NPTS;

    for (int k0 = 0; k0 < CIN; k0 += 32) {
#pragma unroll
        for (int i = 0; i < 8; i++) {
            int e = tid + i * 256;
            sF[e >> 6][e & 63] = fb[(k0 + (e >> 6)) * NPTS + n0 + (e & 63)];
        }
#pragma unroll
        for (int i = 0; i < 16; i++) {
            int e = tid + i * 256;
            sW[e & 31][e >> 5] = W[(o0 + (e >> 5)) * CIN + k0 + (e & 31)];
        }
        __syncthreads();
#pragma unroll
        for (int c = 0; c < 32; c++) {
            float fv[4], wv[8];
#pragma unroll
            for (int i = 0; i < 4; i++) fv[i] = sF[c][tx * 4 + i];
#pragma unroll
            for (int j = 0; j < 8; j++) wv[j] = sW[c][ty * 8 + j];
#pragma unroll
            for (int i = 0; i < 4; i++)
#pragma unroll
                for (int j = 0; j < 8; j++) acc[i][j] += fv[i] * wv[j];
        }
        __syncthreads();
    }

    float* pb = g_pre + b * NPTS * COUT;
#pragma unroll
    for (int i = 0; i < 4; i++) {
        int n = n0 + tx * 4 + i;
#pragma unroll
        for (int j = 0; j < 8; j++)
            pb[n * COUT + o0 + ty * 8 + j] = acc[i][j];
    }
}

// ---------------------------------------------------------------------------
// Worker: SM-exclusion -> drain GEMM queue -> wait all GEMM done ->
// drain MP chunks (8 centers: 8 warps ballquery into smem, then each warp
// max-gathers its center: lane handles 8 channels = 2 float4 columns).
// MP work overlaps the remaining ~300us of FPS, gated on the coarse
// g_prog flags (16 writes/batch total — no hot-path contention).
// ---------------------------------------------------------------------------
__device__ void worker(const float* __restrict__ xyz,
                       const float* __restrict__ feat,
                       const float* __restrict__ W,
                       const float* __restrict__ bconv,
                       const float* __restrict__ gamma,
                       const float* __restrict__ beta,
                       const float* __restrict__ rmean,
                       const float* __restrict__ rvar,
                       float* __restrict__ out) {
    __shared__ float sF[32][65];
    __shared__ float sW[32][129];
    __shared__ int   s_nbr[CHUNK][SSAMP];
    __shared__ int   s_ctl;

    const int tid = threadIdx.x;
    const int lane = tid & 31, warp = tid >> 5;

    if (tid == 0) {
        while (ld_acq(&g_ready) < BSZ) __nanosleep(64);
        int sm = my_smid(), hit = 0;
#pragma unroll
        for (int i = 0; i < BSZ; i++) hit |= (g_smid[i] == sm);
        s_ctl = hit ? -1 : 0;
    }
    __syncthreads();
    if (s_ctl == -1) return;     // keep FPS SMs free

    // Phase 1: GEMM tiles
    for (;;) {
        if (tid == 0) s_ctl = atomicAdd(&g_tile, 1);
        __syncthreads();
        const int t = s_ctl;
        if (t >= NTILES) break;
        gemm_tile(feat, W, t, sF, sW);
        __syncthreads();
        if (tid == 0) { __threadfence(); atomicAdd(&g_gdone, 1); }
        __syncthreads();
    }

    // All of g_pre must be written before any gather
    if (tid == 0)
        while (ld_acq(&g_gdone) < NTILES) __nanosleep(256);
    __syncthreads();

    // Phase 2: ballquery + maxpool chunks (overlapping the rest of FPS)
    for (;;) {
        if (tid == 0) s_ctl = atomicAdd(&g_mpq, 1);
        __syncthreads();
        const int c = s_ctl;
        if (c >= NCHUNK) return;
        const int b  = c & (BSZ - 1);          // spread across batches
        const int m0 = (c >> 3) * CHUNK;
        const float* p = xyz + b * NPTS * 3;

        if (tid == 0)
            while (ld_acq(&g_prog[b]) < m0 + CHUNK) __nanosleep(512);
        __syncthreads();

        // ballquery: warp w -> center m0+w (bit-exact r10 scan)
        {
            const int m = m0 + warp;
            const int ci = __ldcg(&g_fps[b * MCTR + m]);
            const float cx = p[3 * ci + 0], cy = p[3 * ci + 1], cz = p[3 * ci + 2];
            const float R2 = 0.1024f;

            int cnt = 0, firstIdx = 0;
            for (int c0 = 0; c0 < NPTS && cnt < SSAMP; c0 += 32) {
                int n = c0 + lane;
                float d = d2_rn(p[3 * n + 0], p[3 * n + 1], p[3 * n + 2],
                                cx, cy, cz);
                bool in = d < R2;
                unsigned msk = __ballot_sync(0xffffffffu, in);
                if (cnt == 0 && msk) firstIdx = c0 + (__ffs(msk) - 1);
                if (in) {
                    int pos = cnt + __popc(msk & ((1u << lane) - 1u));
                    if (pos < SSAMP) s_nbr[warp][pos] = n * COUT;
                }
                cnt += __popc(msk);
            }
            for (int pos = cnt + lane; pos < SSAMP; pos += 32)
                s_nbr[warp][pos] = firstIdx * COUT;
        }
        __syncwarp();

        // max-gather + folded BN/bias/ReLU: warp w -> center m0+w,
        // lane handles 8 channels (2 float4). Arithmetic identical to r10.
        {
            const int m = m0 + warp;
            const float* pb = g_pre + b * NPTS * COUT + lane * 8;
            float4 mx0 = make_float4(-3.4e38f, -3.4e38f, -3.4e38f, -3.4e38f);
            float4 mx1 = mx0;
#pragma unroll 8
            for (int s = 0; s < SSAMP; s++) {
                const float* q = pb + s_nbr[warp][s];
                const float4 v0 = *(const float4*)(q);
                const float4 v1 = *(const float4*)(q + 4);
                mx0.x = fmaxf(mx0.x, v0.x); mx0.y = fmaxf(mx0.y, v0.y);
                mx0.z = fmaxf(mx0.z, v0.z); mx0.w = fmaxf(mx0.w, v0.w);
                mx1.x = fmaxf(mx1.x, v1.x); mx1.y = fmaxf(mx1.y, v1.y);
                mx1.z = fmaxf(mx1.z, v1.z); mx1.w = fmaxf(mx1.w, v1.w);
            }
#pragma unroll
            for (int h = 0; h < 2; h++) {
                const float4 mx = h ? mx1 : mx0;
                const int oi = lane * 2 + h;
                const float4 bc = ((const float4*)bconv)[oi];
                const float4 gm = ((const float4*)gamma)[oi];
                const float4 bt = ((const float4*)beta )[oi];
                const float4 rm = ((const float4*)rmean)[oi];
                const float4 rv = ((const float4*)rvar )[oi];
                const int o = oi * 4;
                out[(b * COUT + o + 0) * MCTR + m] =
                    fmaxf((mx.x + bc.x - rm.x) * (gm.x * rsqrtf(rv.x + 1e-5f)) + bt.x, 0.f);
                out[(b * COUT + o + 1) * MCTR + m] =
                    fmaxf((mx.y + bc.y - rm.y) * (gm.y * rsqrtf(rv.y + 1e-5f)) + bt.y, 0.f);
                out[(b * COUT + o + 2) * MCTR + m] =
                    fmaxf((mx.z + bc.z - rm.z) * (gm.z * rsqrtf(rv.z + 1e-5f)) + bt.z, 0.f);
                out[(b * COUT + o + 3) * MCTR + m] =
                    fmaxf((mx.w + bc.w - rm.w) * (gm.w * rsqrtf(rv.w + 1e-5f)) + bt.w, 0.f);
            }
        }
        __syncthreads();
    }
}

// ---------------------------------------------------------------------------
__global__ __launch_bounds__(256) void fused_kernel(
    const float* __restrict__ xyz,  const float* __restrict__ feat,
    const float* __restrict__ W,    const float* __restrict__ bconv,
    const float* __restrict__ gamma,const float* __restrict__ beta,
    const float* __restrict__ rmean,const float* __restrict__ rvar,
    float* __restrict__ out) {
    if (blockIdx.x < BSZ)
        fps_body(xyz, blockIdx.x);
    else
        worker(xyz, feat, W, bconv, gamma, beta, rmean, rvar, out);
}

// ---------------------------------------------------------------------------
extern "C" void kernel_launch(void* const* d_in, const int* in_sizes, int n_in,
                              void* d_out, int out_size) {
    const float* xyz  = (const float*)d_in[0];
    const float* feat = (const float*)d_in[1];
    const float* W    = (const float*)d_in[2];
    const float* bcv  = (const float*)d_in[3];
    const float* gm   = (const float*)d_in[4];
    const float* bt   = (const float*)d_in[5];
    const float* rm   = (const float*)d_in[6];
    const float* rv   = (const float*)d_in[7];
    float* out = (float*)d_out;

    reset_kernel<<<1, 32>>>();
    fused_kernel<<<BSZ + NTILES, 256>>>(xyz, feat, W, bcv, gm, bt, rm, rv, out);
}

// round 15
// speedup vs baseline: 1.1569x; 1.1569x over previous
#include <cuda_runtime.h>

#define BSZ   8
#define NPTS  4096
#define CIN   128
#define COUT  256
#define MCTR  1024
#define SSAMP 64
#define NTILES 1024     // (NPTS/64)*(COUT/128)*BSZ

// Scratch (static device globals: no allocations allowed)
__device__ float g_pre[BSZ * NPTS * COUT];   // [b][n][o]  33.5 MB
__device__ int   g_fps[BSZ * MCTR];
__device__ int   g_idx[BSZ * MCTR * SSAMP];
__device__ int   g_smid[BSZ];                // SMs hosting FPS blocks
__device__ int   g_ready;                    // FPS blocks that published smid
__device__ int   g_tile;                     // GEMM tile work queue head

// Exact reference arithmetic: squares then left-to-right sum, no FMA contraction.
__device__ __forceinline__ float d2_rn(float ax, float ay, float az,
                                       float bx, float by, float bz) {
    float dx = ax - bx, dy = ay - by, dz = az - bz;
    return __fadd_rn(__fadd_rn(__fmul_rn(dx, dx), __fmul_rn(dy, dy)),
                     __fmul_rn(dz, dz));
}

// ---- packed f32x2 helpers (per-lane IEEE rn: bit-identical to scalar) ----
__device__ __forceinline__ unsigned long long pack2(float lo, float hi) {
    unsigned long long r;
    asm("mov.b64 %0, {%1, %2};" : "=l"(r) : "f"(lo), "f"(hi));
    return r;
}
__device__ __forceinline__ void unpack2(unsigned long long v, float& lo, float& hi) {
    asm("mov.b64 {%0, %1}, %2;" : "=f"(lo), "=f"(hi) : "l"(v));
}
__device__ __forceinline__ unsigned long long add2(unsigned long long a,
                                                   unsigned long long b) {
    unsigned long long r;
    asm("add.rn.f32x2 %0, %1, %2;" : "=l"(r) : "l"(a), "l"(b));
    return r;
}
__device__ __forceinline__ unsigned long long mul2(unsigned long long a,
                                                   unsigned long long b) {
    unsigned long long r;
    asm("mul.rn.f32x2 %0, %1, %2;" : "=l"(r) : "l"(a), "l"(b));
    return r;
}

__device__ __forceinline__ int ld_acq(const int* p) {
    int v;
    asm volatile("ld.acquire.gpu.global.s32 %0, [%1];" : "=r"(v) : "l"(p) : "memory");
    return v;
}
__device__ __forceinline__ int my_smid() {
    int s; asm("mov.u32 %0, %%smid;" : "=r"(s)); return s;
}

// ---------------------------------------------------------------------------
__global__ void reset_kernel() {
    if (threadIdx.x == 0) { g_ready = 0; g_tile = 0; }
}

// ---------------------------------------------------------------------------
// FPS (r10 champion, verbatim): 256 threads x 16 points, packed f32x2 bulk,
// REDUX argmax, atomicMin tie-break, parity double-buffered winner slot.
// Publishes its %smid at start so GEMM blocks can avoid these SMs.
// No per-iteration cross-block publication of any kind (measured poison).
// ---------------------------------------------------------------------------
__device__ void fps_body(const float* __restrict__ xyz, int b) {
    const int tid = threadIdx.x;
    const int lane = tid & 31, warp = tid >> 5;

    __shared__ int s_wv[8];
    __shared__ int s_widx[2];

    if (tid == 0) {
        g_smid[b] = my_smid();
        __threadfence();
        atomicAdd(&g_ready, 1);
    }

    const float* p = xyz + b * NPTS * 3;

    unsigned long long px2[8], py2[8], pz2[8];
    float mind[16];
#pragma unroll
    for (int j = 0; j < 8; j++) {
        int n0 = (2 * j) * 256 + tid;
        int n1 = (2 * j + 1) * 256 + tid;
        px2[j] = pack2(p[3 * n0 + 0], p[3 * n1 + 0]);
        py2[j] = pack2(p[3 * n0 + 1], p[3 * n1 + 1]);
        pz2[j] = pack2(p[3 * n0 + 2], p[3 * n1 + 2]);
        mind[2 * j] = 1e10f; mind[2 * j + 1] = 1e10f;
    }
    if (tid == 0) s_widx[0] = 0;   // idx[0] = 0
    __syncthreads();

    for (int t = 1; t < MCTR; t++) {
        const int Iv = s_widx[(t - 1) & 1];
        if (tid == 0) {
            g_fps[b * MCTR + t - 1] = Iv;
            s_widx[t & 1] = 0x7fffffff;
        }
        const float lx = __ldg(p + 3 * Iv + 0);
        const float ly = __ldg(p + 3 * Iv + 1);
        const float lz = __ldg(p + 3 * Iv + 2);
        const unsigned long long nlx2 = pack2(-lx, -lx);
        const unsigned long long nly2 = pack2(-ly, -ly);
        const unsigned long long nlz2 = pack2(-lz, -lz);

#pragma unroll
        for (int j = 0; j < 8; j++) {
            unsigned long long dx2 = add2(px2[j], nlx2);
            unsigned long long dy2 = add2(py2[j], nly2);
            unsigned long long dz2 = add2(pz2[j], nlz2);
            unsigned long long s2 = add2(add2(mul2(dx2, dx2), mul2(dy2, dy2)),
                                         mul2(dz2, dz2));
            float s0, s1; unpack2(s2, s0, s1);
            mind[2 * j]     = fminf(mind[2 * j],     s0);
            mind[2 * j + 1] = fminf(mind[2 * j + 1], s1);
        }

        float m01 = fmaxf(mind[0], mind[1]),   m23 = fmaxf(mind[2], mind[3]);
        float m45 = fmaxf(mind[4], mind[5]),   m67 = fmaxf(mind[6], mind[7]);
        float m89 = fmaxf(mind[8], mind[9]),   mab = fmaxf(mind[10], mind[11]);
        float mcd = fmaxf(mind[12], mind[13]), mef = fmaxf(mind[14], mind[15]);
        float q0 = fmaxf(m01, m23), q1 = fmaxf(m45, m67);
        float q2 = fmaxf(m89, mab), q3 = fmaxf(mcd, mef);
        float best = fmaxf(fmaxf(q0, q1), fmaxf(q2, q3));

        const int tb   = __float_as_int(best);
        const int wmax = __reduce_max_sync(0xffffffffu, tb);
        if (lane == 0) s_wv[warp] = wmax;
        __syncthreads();

        int vb = (lane < 8) ? s_wv[lane] : (int)0x80000000;
        const int bmax = __reduce_max_sync(0xffffffffu, vb);

        if (tb == bmax) {  // rare: winner thread(s) resolve lowest index
            int n = 0x7fffffff;
#pragma unroll
            for (int k = 15; k >= 0; k--)
                if (__float_as_int(mind[k]) == bmax) n = k * 256 + tid;
            atomicMin(&s_widx[t & 1], n);
        }
        __syncthreads();
    }
    if (tid == 0) g_fps[b * MCTR + MCTR - 1] = s_widx[(MCTR - 1) & 1];
}

// ---------------------------------------------------------------------------
// One GEMM tile (r10 champion): pre[b][n][o] = sum_c feat[b][c][n] * W[o][c].
// ---------------------------------------------------------------------------
__device__ void gemm_tile(const float* __restrict__ feat,
                          const float* __restrict__ W, int gid,
                          float sF[32][65], float sW[32][129]) {
    const int b    = gid >> 7;
    const int rest = gid & 127;
    const int o0   = (rest & 1) * 128;
    const int n0   = (rest >> 1) * 64;

    const int tid = threadIdx.x;
    const int tx = tid & 15;
    const int ty = tid >> 4;

    float acc[4][8];
#pragma unroll
    for (int i = 0; i < 4; i++)
#pragma unroll
        for (int j = 0; j < 8; j++) acc[i][j] = 0.f;

    const float* fb = feat + b * CIN * NPTS;

    for (int k0 = 0; k0 < CIN; k0 += 32) {
#pragma unroll
        for (int i = 0; i < 8; i++) {
            int e = tid + i * 256;
            sF[e >> 6][e & 63] = fb[(k0 + (e >> 6)) * NPTS + n0 + (e & 63)];
        }
#pragma unroll
        for (int i = 0; i < 16; i++) {
            int e = tid + i * 256;
            sW[e & 31][e >> 5] = W[(o0 + (e >> 5)) * CIN + k0 + (e & 31)];
        }
        __syncthreads();
#pragma unroll
        for (int c = 0; c < 32; c++) {
            float fv[4], wv[8];
#pragma unroll
            for (int i = 0; i < 4; i++) fv[i] = sF[c][tx * 4 + i];
#pragma unroll
            for (int j = 0; j < 8; j++) wv[j] = sW[c][ty * 8 + j];
#pragma unroll
            for (int i = 0; i < 4; i++)
#pragma unroll
                for (int j = 0; j < 8; j++) acc[i][j] += fv[i] * wv[j];
        }
        __syncthreads();
    }

    float* pb = g_pre + b * NPTS * COUT;
#pragma unroll
    for (int i = 0; i < 4; i++) {
        int n = n0 + tx * 4 + i;
#pragma unroll
        for (int j = 0; j < 8; j++)
            pb[n * COUT + o0 + ty * 8 + j] = acc[i][j];
    }
}

// ---------------------------------------------------------------------------
// GEMM worker (r10 champion): exclude FPS SMs, then drain the tile queue.
// ---------------------------------------------------------------------------
__device__ void gemm_worker(const float* __restrict__ feat,
                            const float* __restrict__ W) {
    __shared__ float sF[32][65];
    __shared__ float sW[32][129];
    __shared__ int   s_ctl;

    const int tid = threadIdx.x;
    if (tid == 0) {
        while (ld_acq(&g_ready) < BSZ) __nanosleep(64);
        int sm = my_smid(), hit = 0;
#pragma unroll
        for (int i = 0; i < BSZ; i++) hit |= (g_smid[i] == sm);
        s_ctl = hit ? -1 : 0;
    }
    __syncthreads();
    if (s_ctl == -1) return;     // keep FPS SMs free of GEMM work

    for (;;) {
        if (tid == 0) s_ctl = atomicAdd(&g_tile, 1);
        __syncthreads();
        const int t = s_ctl;
        if (t >= NTILES) return;
        gemm_tile(feat, W, t, sF, sW);
        __syncthreads();
    }
}

// ---------------------------------------------------------------------------
__global__ __launch_bounds__(256) void fused_fps_gemm_kernel(
    const float* __restrict__ xyz, const float* __restrict__ feat,
    const float* __restrict__ W) {
    if (blockIdx.x < BSZ) fps_body(xyz, blockIdx.x);
    else                  gemm_worker(feat, W);
}

// ---------------------------------------------------------------------------
// Ball query (r10 verbatim): one warp per (b,m) center.
// ---------------------------------------------------------------------------
__global__ __launch_bounds__(256) void ballquery_kernel(const float* __restrict__ xyz) {
    const int tid = threadIdx.x, lane = tid & 31, w = tid >> 5;
    const int gw = blockIdx.x * 8 + w;
    const int b = gw >> 10, m = gw & (MCTR - 1);
    const float* p = xyz + b * NPTS * 3;

    const int ci = g_fps[b * MCTR + m];
    const float cx = p[3 * ci + 0], cy = p[3 * ci + 1], cz = p[3 * ci + 2];
    const float R2 = 0.1024f;

    int cnt = 0, firstIdx = 0;
    int* dst = g_idx + (b * MCTR + m) * SSAMP;

    for (int c0 = 0; c0 < NPTS && cnt < SSAMP; c0 += 32) {
        int n = c0 + lane;
        float d = d2_rn(p[3 * n + 0], p[3 * n + 1], p[3 * n + 2], cx, cy, cz);
        bool in = d < R2;
        unsigned msk = __ballot_sync(0xffffffffu, in);
        if (cnt == 0 && msk) firstIdx = c0 + (__ffs(msk) - 1);
        if (in) {
            int pos = cnt + __popc(msk & ((1u << lane) - 1u));
            if (pos < SSAMP) dst[pos] = n;
        }
        cnt += __popc(msk);
    }
    for (int pos = cnt + lane; pos < SSAMP; pos += 32) dst[pos] = firstIdx;
}

// ---------------------------------------------------------------------------
// Max-gather + folded BN/bias/ReLU (r13 variant — best measured: 36.7us):
// 128 threads per block, two centers per block, gather unrolled 16.
// L2-bandwidth bound at the LTS ceiling; arithmetic identical to r10.
// ---------------------------------------------------------------------------
__global__ __launch_bounds__(128) void maxpool_kernel(
    const float* __restrict__ bconv, const float* __restrict__ gamma,
    const float* __restrict__ beta,  const float* __restrict__ rmean,
    const float* __restrict__ rvar,  float* __restrict__ out) {
    const int b = blockIdx.y, tid = threadIdx.x;
    const int c = tid >> 6;              // center-in-block (0/1)
    const int ctid = tid & 63;           // thread-in-center
    const int m = blockIdx.x * 2 + c;

    __shared__ int soff[2][SSAMP];
    soff[c][ctid] = g_idx[(b * MCTR + m) * SSAMP + ctid] * COUT;
    __syncthreads();

    const float* pb = g_pre + b * NPTS * COUT + ctid * 4;
    float4 mx = make_float4(-3.4e38f, -3.4e38f, -3.4e38f, -3.4e38f);
#pragma unroll 16
    for (int s = 0; s < SSAMP; s++) {
        const float4 v = *(const float4*)(pb + soff[c][s]);
        mx.x = fmaxf(mx.x, v.x); mx.y = fmaxf(mx.y, v.y);
        mx.z = fmaxf(mx.z, v.z); mx.w = fmaxf(mx.w, v.w);
    }

    const float4 bc = ((const float4*)bconv)[ctid];
    const float4 gm = ((const float4*)gamma)[ctid];
    const float4 bt = ((const float4*)beta )[ctid];
    const float4 rm = ((const float4*)rmean)[ctid];
    const float4 rv = ((const float4*)rvar )[ctid];

    const int o = ctid * 4;
    out[(b * COUT + o + 0) * MCTR + m] =
        fmaxf((mx.x + bc.x - rm.x) * (gm.x * rsqrtf(rv.x + 1e-5f)) + bt.x, 0.f);
    out[(b * COUT + o + 1) * MCTR + m] =
        fmaxf((mx.y + bc.y - rm.y) * (gm.y * rsqrtf(rv.y + 1e-5f)) + bt.y, 0.f);
    out[(b * COUT + o + 2) * MCTR + m] =
        fmaxf((mx.z + bc.z - rm.z) * (gm.z * rsqrtf(rv.z + 1e-5f)) + bt.z, 0.f);
    out[(b * COUT + o + 3) * MCTR + m] =
        fmaxf((mx.w + bc.w - rm.w) * (gm.w * rsqrtf(rv.w + 1e-5f)) + bt.w, 0.f);
}

// ---------------------------------------------------------------------------
extern "C" void kernel_launch(void* const* d_in, const int* in_sizes, int n_in,
                              void* d_out, int out_size) {
    const float* xyz  = (const float*)d_in[0];
    const float* feat = (const float*)d_in[1];
    const float* W    = (const float*)d_in[2];
    const float* bcv  = (const float*)d_in[3];
    const float* gm   = (const float*)d_in[4];
    const float* bt   = (const float*)d_in[5];
    const float* rm   = (const float*)d_in[6];
    const float* rv   = (const float*)d_in[7];
    float* out = (float*)d_out;

    reset_kernel<<<1, 32>>>();
    fused_fps_gemm_kernel<<<BSZ + NTILES, 256>>>(xyz, feat, W);
    ballquery_kernel<<<(BSZ * MCTR) / 8, 256>>>(xyz);
    maxpool_kernel<<<dim3(MCTR / 2, BSZ), 128>>>(bcv, gm, bt, rm, rv, out);
}